// round 16
// baseline (speedup 1.0000x reference)
#include <cuda_runtime.h>
#include <cstddef>
#include <cstdint>

// Problem constants (fixed shapes from setup_inputs)
#define C_    32
#define H_    192
#define W_    256
#define S_    9
#define G_    8
#define HW_   (H_*W_)            // 49152
#define HWS_  ((size_t)HW_*S_)   // 442368
#define CHWS_ ((size_t)C_*HWS_)

#define TPB_A 128                // att1: pixels per CTA
#define CS    4                  // att1: channel slices (8 channels each)
#define CPS   (C_/CS)            // 8 channels per slice
#define TPB_B 128                // stream kernel: pixels per CTA
#define NSPL  8                  // source-image split (launch-adjacent grid.x)
#define NT    2                  // tiles per stage in stream kernel: ref + 1 src
#define T4A   (TPB_A*S_/4)       // float4 per att tile = 288
#define T4    (TPB_B*S_/4)       // float4 per stream tile = 288
#define RING  3                  // pipeline stages

__device__ float g_att[S_ * HW_];        // att, SoA: [s][p]
__device__ float g_lpart[CS * S_ * HW_]; // partial logits: [y][s][p]

// ---- cp.async helpers ----
__device__ __forceinline__ void cp16(uint32_t dst, const void* src) {
    asm volatile("cp.async.cg.shared.global [%0], [%1], 16;\n" :: "r"(dst), "l"(src));
}
__device__ __forceinline__ void cp_commit() {
    asm volatile("cp.async.commit_group;\n" ::: "memory");
}
template<int N> __device__ __forceinline__ void cp_wait() {
    asm volatile("cp.async.wait_group %0;\n" :: "n"(N) : "memory");
}

// ---------------- att1: partial logits over an 8-channel slice ----------------
__global__ void __launch_bounds__(TPB_A, 6)
att1_kernel(const float* __restrict__ f, const float* __restrict__ Wp,
            const float* __restrict__ bp) {
    __shared__ float  Wsm[C_*C_];          // Wp row-major [d][c], 4 KB
    __shared__ float4 ring[RING][T4A];     // 3 * 288 float4 = 13.8 KB

    const int tid = threadIdx.x;
    const int p0  = blockIdx.x * TPB_A;
    const int p   = p0 + tid;
    const int y   = blockIdx.y;            // channel slice
    const int c0  = y * CPS;

    {   // stage Wp (256 float4 / 128 threads)
        float4* W4 = (float4*)Wsm;
        const float4* Wg = (const float4*)Wp;
        W4[tid]       = Wg[tid];
        W4[tid + 128] = Wg[tid + 128];
    }

    const uint32_t ring_s = (uint32_t)__cvta_generic_to_shared(&ring[0][0]);
    auto issue = [&](int cc, int slot) {
        const uint32_t base = ring_s + (uint32_t)slot * (T4A*16);
        const char* g = (const char*)(f + (size_t)(c0+cc)*HWS_ + (size_t)p0*S_);
        cp16(base + (uint32_t)tid*16,           g + (size_t)tid*16);
        cp16(base + (uint32_t)(tid+TPB_A)*16,   g + (size_t)(tid+TPB_A)*16);
        if (tid < T4A - 2*TPB_A)                // 32 remaining
            cp16(base + (uint32_t)(tid+2*TPB_A)*16, g + (size_t)(tid+2*TPB_A)*16);
        cp_commit();
    };

    issue(0, 0);
    issue(1, 1);
    __syncthreads();           // Wsm visible

    // u = Wp rm + bp  (rm scoped: dies before the logit loop)
    float u[C_];
    {
        float rm[C_];
        #pragma unroll
        for (int c = 0; c < C_; c++)
            rm[c] = __ldg(f + (size_t)c*HWS_ + (size_t)p*S_ + 4);
        #pragma unroll
        for (int d = 0; d < C_; d++) {
            float a0 = 0.f, a1 = 0.f;
            const float* row = Wsm + d*C_;
            #pragma unroll
            for (int c = 0; c < C_; c += 2) {
                a0 += row[c]   * rm[c];
                a1 += row[c+1] * rm[c+1];
            }
            u[d] = (a0 + a1) + __ldg(bp + d);
        }
    }

    float l[S_];
    #pragma unroll
    for (int s = 0; s < S_; s++) l[s] = 0.f;

    #pragma unroll 1
    for (int cc = 0; cc < CPS; cc++) {
        cp_wait<1>();
        __syncthreads();       // slot cc%3 visible; slot (cc+2)%3 consumed
        if (cc + 2 < CPS) issue(cc + 2, (cc + 2) % RING);
        else              cp_commit();   // keep group-count aligned

        // tvc = sum_d u[d]*Wp[d][c0+cc]  (uniform SMEM reads -> broadcast)
        float t0 = 0.f, t1 = 0.f;
        #pragma unroll
        for (int d = 0; d < C_; d += 2) {
            t0 += u[d]   * Wsm[d*C_ + c0 + cc];
            t1 += u[d+1] * Wsm[(d+1)*C_ + c0 + cc];
        }
        const float tvc = t0 + t1;

        const float* r = (const float*)&ring[cc % RING][0] + tid*S_;  // bank-clean
        #pragma unroll
        for (int s = 0; s < S_; s++) l[s] += tvc * r[s];
    }

    #pragma unroll
    for (int s = 0; s < S_; s++)
        g_lpart[((size_t)y*S_ + s)*HW_ + p] = l[s];
}

// ---------------- att2: reduce partials + softmax ----------------
__global__ void __launch_bounds__(256, 8)
att2_kernel() {
    const int p = blockIdx.x * 256 + threadIdx.x;

    float l[S_];
    #pragma unroll
    for (int s = 0; s < S_; s++) l[s] = 0.f;
    #pragma unroll
    for (int y = 0; y < CS; y++)
        #pragma unroll
        for (int s = 0; s < S_; s++)
            l[s] += g_lpart[((size_t)y*S_ + s)*HW_ + p];

    const float inv_sqrtC = 0.17677669529663687f;   // 1/sqrt(32)
    float mx = l[0];
    #pragma unroll
    for (int s = 1; s < S_; s++) mx = fmaxf(mx, l[s]);
    float e[S_], sum = 0.f;
    #pragma unroll
    for (int s = 0; s < S_; s++) { e[s] = __expf((l[s] - mx) * inv_sqrtC); sum += e[s]; }
    const float isum = __frcp_rn(sum);
    #pragma unroll
    for (int s = 0; s < S_; s++) g_att[s * HW_ + p] = e[s] * isum;
}

// ---------------- kernel B: cp.async-pipelined source streaming ----------------
// grid = (NSPL, HW/TPB): the 8 n-copies of a pixel block are launch-ADJACENT,
// so ref tiles are DRAM-fetched once and L2-hit by the other 7 copies.
__global__ void __launch_bounds__(TPB_B, 8)
stream_kernel(const float* __restrict__ f, float* __restrict__ out) {
    __shared__ float4 ring[RING][NT*T4];   // 3 * 2 * 288 float4 = 27648 B

    const int tid = threadIdx.x;
    const int n0  = blockIdx.x;            // source image (0..7)
    const int p0  = blockIdx.y * TPB_B;
    const int p   = p0 + tid;

    float att[S_];
    #pragma unroll
    for (int s = 0; s < S_; s++) att[s] = __ldg(&g_att[s * HW_ + p]);

    const uint32_t ring_s = (uint32_t)__cvta_generic_to_shared(&ring[0][0]);

    auto issue = [&](int c, int slot) {
        const uint32_t base = ring_s + (uint32_t)slot * (NT*T4*16);
        #pragma unroll
        for (int t = 0; t < NT; t++) {
            const int img = (t == 0) ? 0 : (n0 + 1);   // ref, then source image n0
            const char* g = (const char*)(f + (size_t)img*CHWS_ + (size_t)c*HWS_ + (size_t)p0*S_);
            const uint32_t d = base + (uint32_t)t * (T4*16);
            cp16(d + (uint32_t)tid*16,            g + (size_t)tid*16);
            cp16(d + (uint32_t)(tid+TPB_B)*16,    g + (size_t)(tid+TPB_B)*16);
            if (tid < T4 - 2*TPB_B)               // 32 remaining
                cp16(d + (uint32_t)(tid+2*TPB_B)*16, g + (size_t)(tid+2*TPB_B)*16);
        }
        cp_commit();
    };

    issue(0, 0);
    issue(1, 1);

    float acc = 0.f;
    #pragma unroll 1
    for (int c = 0; c < C_; c++) {
        cp_wait<1>();          // group c complete (slot c%3 ready)
        __syncthreads();       // visible to all; slot (c+2)%3 fully consumed

        if (c + 2 < C_) issue(c + 2, (c + 2) % RING);
        else            cp_commit();   // keep wait_group<1> semantics aligned

        const float* sf = (const float*)&ring[c % RING][0];
        const float* rr = sf + tid*S_;                // ref row (bank-clean)
        const float* sn = sf + (TPB_B*S_) + tid*S_;   // src row
        float a = 0.f;
        #pragma unroll
        for (int s = 0; s < S_; s++) a += (rr[s] * att[s]) * sn[s];
        acc += a;

        if ((c & 3) == 3) {
            out[(size_t)(n0*G_ + (c >> 2))*HW_ + p] = acc;
            acc = 0.f;
        }
    }
}

extern "C" void kernel_launch(void* const* d_in, const int* in_sizes, int n_in,
                              void* d_out, int out_size) {
    // Identify inputs by element count: f = 127401984, Wp = 1024, bp = 32
    const float* f  = nullptr;
    const float* Wp = nullptr;
    const float* bp = nullptr;
    for (int i = 0; i < n_in; i++) {
        if      (in_sizes[i] == 127401984) f  = (const float*)d_in[i];
        else if (in_sizes[i] == 1024)      Wp = (const float*)d_in[i];
        else if (in_sizes[i] == 32)        bp = (const float*)d_in[i];
    }
    if (!f || !Wp || !bp) {  // fallback positional
        f  = (const float*)d_in[0];
        Wp = (const float*)d_in[1];
        bp = (const float*)d_in[2];
    }
    float* out = (float*)d_out;

    dim3 gridA(HW_/TPB_A, CS);
    att1_kernel<<<gridA, TPB_A>>>(f, Wp, bp);
    att2_kernel<<<HW_/256, 256>>>();
    dim3 gridB(NSPL, HW_/TPB_B);
    stream_kernel<<<gridB, TPB_B>>>(f, out);
}

// round 17
// speedup vs baseline: 1.1623x; 1.1623x over previous
#include <cuda_runtime.h>
#include <cstddef>
#include <cstdint>

// Problem constants (fixed shapes from setup_inputs)
#define C_    32
#define H_    192
#define W_    256
#define S_    9
#define G_    8
#define HW_   (H_*W_)            // 49152
#define HWS_  ((size_t)HW_*S_)   // 442368
#define CHWS_ ((size_t)C_*HWS_)

#define TPB_A 128                // att: pixels per CTA
#define TPB_B 128                // stream kernel: pixels per CTA
#define NSPL  8                  // source-image split (launch-adjacent grid.x)
#define NT    2                  // tiles per stage in stream kernel: ref + 1 src
#define T4A   (TPB_A*S_/4)       // float4 per att tile = 288
#define T4    (TPB_B*S_/4)       // float4 per stream tile = 288
#define RINGA 4                  // att pipeline stages (lookahead 2)
#define RING  3                  // stream pipeline stages

__device__ float g_att[S_ * HW_];   // att, SoA: [s][p]

// ---- cp.async helpers ----
__device__ __forceinline__ void cp16(uint32_t dst, const void* src) {
    asm volatile("cp.async.cg.shared.global [%0], [%1], 16;\n" :: "r"(dst), "l"(src));
}
__device__ __forceinline__ void cp_commit() {
    asm volatile("cp.async.commit_group;\n" ::: "memory");
}
template<int N> __device__ __forceinline__ void cp_wait() {
    asm volatile("cp.async.wait_group %0;\n" :: "n"(N) : "memory");
}

// ---------------- att kernel: single-pass, float4-LDS matvecs, depth-2 ring ----------------
__global__ void __launch_bounds__(TPB_A, 4)
att_kernel(const float* __restrict__ f, const float* __restrict__ Wp,
           const float* __restrict__ bp) {
    __shared__ float  Wsm[C_*C_];          // Wp  [d][c]   4 KB
    __shared__ float  WT [C_*C_];          // Wp^T [c][d]  4 KB
    __shared__ float4 ring[RINGA][T4A];    // 4 * 288 float4 = 18.4 KB

    const int tid = threadIdx.x;
    const int p0  = blockIdx.x * TPB_A;
    const int p   = p0 + tid;

    const uint32_t ring_s = (uint32_t)__cvta_generic_to_shared(&ring[0][0]);
    auto issue = [&](int c, int slot) {
        const uint32_t base = ring_s + (uint32_t)slot * (T4A*16);
        const char* g = (const char*)(f + (size_t)c*HWS_ + (size_t)p0*S_);
        cp16(base + (uint32_t)tid*16,           g + (size_t)tid*16);
        cp16(base + (uint32_t)(tid+TPB_A)*16,   g + (size_t)(tid+TPB_A)*16);
        if (tid < T4A - 2*TPB_A)                // 32 remaining
            cp16(base + (uint32_t)(tid+2*TPB_A)*16, g + (size_t)(tid+2*TPB_A)*16);
        cp_commit();
    };

    // prefetch c = 0,1,2 (lookahead 2 steps)
    issue(0, 0);
    issue(1, 1);
    issue(2, 2);

    {   // stage Wp (256 float4 / 128 threads)
        float4* W4 = (float4*)Wsm;
        const float4* Wg = (const float4*)Wp;
        W4[tid]       = Wg[tid];
        W4[tid + 128] = Wg[tid + 128];
    }
    __syncthreads();
    {   // build Wp^T (one-time scalar shuffle, 8 elems/thread)
        #pragma unroll
        for (int k = 0; k < 8; k++) {
            const int idx = tid*8 + k;                // idx = d*32 + c
            WT[(idx & 31)*C_ + (idx >> 5)] = Wsm[idx];
        }
    }
    __syncthreads();

    // u = Wp rm + bp  (float4 LDS rows; rm scoped so it dies here)
    float u[C_];
    {
        float rm[C_];
        #pragma unroll
        for (int c = 0; c < C_; c++)
            rm[c] = __ldg(f + (size_t)c*HWS_ + (size_t)p*S_ + 4);
        #pragma unroll
        for (int d = 0; d < C_; d++) {
            const float4* row4 = (const float4*)(Wsm + d*C_);
            float a0 = 0.f, a1 = 0.f;
            #pragma unroll
            for (int q = 0; q < C_/4; q += 2) {
                float4 w0 = row4[q], w1 = row4[q+1];
                a0 += w0.x*rm[4*q]   + w0.y*rm[4*q+1] + w0.z*rm[4*q+2] + w0.w*rm[4*q+3];
                a1 += w1.x*rm[4*q+4] + w1.y*rm[4*q+5] + w1.z*rm[4*q+6] + w1.w*rm[4*q+7];
            }
            u[d] = (a0 + a1) + __ldg(bp + d);
        }
    }

    float l[S_];
    #pragma unroll
    for (int s = 0; s < S_; s++) l[s] = 0.f;

    #pragma unroll 1
    for (int c = 0; c < C_; c++) {
        cp_wait<2>();          // group c complete (slot c%4 ready)
        __syncthreads();       // visible; slot (c+3)%4 fully consumed at step c-1
        if (c + 3 < C_) issue(c + 3, (c + 3) % RINGA);
        else            cp_commit();   // keep group-count semantics aligned

        // tvc = sum_d u[d] * WT[c][d]   (float4 LDS, uniform -> broadcast)
        const float4* wt4 = (const float4*)(WT + c*C_);
        float t0 = 0.f, t1 = 0.f;
        #pragma unroll
        for (int q = 0; q < C_/4; q += 2) {
            float4 w0 = wt4[q], w1 = wt4[q+1];
            t0 += w0.x*u[4*q]   + w0.y*u[4*q+1] + w0.z*u[4*q+2] + w0.w*u[4*q+3];
            t1 += w1.x*u[4*q+4] + w1.y*u[4*q+5] + w1.z*u[4*q+6] + w1.w*u[4*q+7];
        }
        const float tvc = t0 + t1;

        const float* r = (const float*)&ring[c % RINGA][0] + tid*S_;  // bank-clean
        #pragma unroll
        for (int s = 0; s < S_; s++) l[s] += tvc * r[s];
    }

    // softmax over s (shift-invariant terms dropped)
    const float inv_sqrtC = 0.17677669529663687f;   // 1/sqrt(32)
    float mx = l[0];
    #pragma unroll
    for (int s = 1; s < S_; s++) mx = fmaxf(mx, l[s]);
    float e[S_], sum = 0.f;
    #pragma unroll
    for (int s = 0; s < S_; s++) { e[s] = __expf((l[s] - mx) * inv_sqrtC); sum += e[s]; }
    const float isum = __frcp_rn(sum);
    #pragma unroll
    for (int s = 0; s < S_; s++) g_att[s * HW_ + p] = e[s] * isum;
}

// ---------------- kernel B: cp.async-pipelined source streaming (UNCHANGED) ----------------
// grid = (NSPL, HW/TPB): the 8 n-copies of a pixel block are launch-ADJACENT,
// so ref tiles are DRAM-fetched once and L2-hit by the other 7 copies.
__global__ void __launch_bounds__(TPB_B, 8)
stream_kernel(const float* __restrict__ f, float* __restrict__ out) {
    __shared__ float4 ring[RING][NT*T4];   // 3 * 2 * 288 float4 = 27648 B

    const int tid = threadIdx.x;
    const int n0  = blockIdx.x;            // source image (0..7)
    const int p0  = blockIdx.y * TPB_B;
    const int p   = p0 + tid;

    float att[S_];
    #pragma unroll
    for (int s = 0; s < S_; s++) att[s] = __ldg(&g_att[s * HW_ + p]);

    const uint32_t ring_s = (uint32_t)__cvta_generic_to_shared(&ring[0][0]);

    auto issue = [&](int c, int slot) {
        const uint32_t base = ring_s + (uint32_t)slot * (NT*T4*16);
        #pragma unroll
        for (int t = 0; t < NT; t++) {
            const int img = (t == 0) ? 0 : (n0 + 1);   // ref, then source image n0
            const char* g = (const char*)(f + (size_t)img*CHWS_ + (size_t)c*HWS_ + (size_t)p0*S_);
            const uint32_t d = base + (uint32_t)t * (T4*16);
            cp16(d + (uint32_t)tid*16,            g + (size_t)tid*16);
            cp16(d + (uint32_t)(tid+TPB_B)*16,    g + (size_t)(tid+TPB_B)*16);
            if (tid < T4 - 2*TPB_B)               // 32 remaining
                cp16(d + (uint32_t)(tid+2*TPB_B)*16, g + (size_t)(tid+2*TPB_B)*16);
        }
        cp_commit();
    };

    issue(0, 0);
    issue(1, 1);

    float acc = 0.f;
    #pragma unroll 1
    for (int c = 0; c < C_; c++) {
        cp_wait<1>();          // group c complete (slot c%3 ready)
        __syncthreads();       // visible to all; slot (c+2)%3 fully consumed

        if (c + 2 < C_) issue(c + 2, (c + 2) % RING);
        else            cp_commit();   // keep wait_group<1> semantics aligned

        const float* sf = (const float*)&ring[c % RING][0];
        const float* rr = sf + tid*S_;                // ref row (bank-clean)
        const float* sn = sf + (TPB_B*S_) + tid*S_;   // src row
        float a = 0.f;
        #pragma unroll
        for (int s = 0; s < S_; s++) a += (rr[s] * att[s]) * sn[s];
        acc += a;

        if ((c & 3) == 3) {
            out[(size_t)(n0*G_ + (c >> 2))*HW_ + p] = acc;
            acc = 0.f;
        }
    }
}

extern "C" void kernel_launch(void* const* d_in, const int* in_sizes, int n_in,
                              void* d_out, int out_size) {
    // Identify inputs by element count: f = 127401984, Wp = 1024, bp = 32
    const float* f  = nullptr;
    const float* Wp = nullptr;
    const float* bp = nullptr;
    for (int i = 0; i < n_in; i++) {
        if      (in_sizes[i] == 127401984) f  = (const float*)d_in[i];
        else if (in_sizes[i] == 1024)      Wp = (const float*)d_in[i];
        else if (in_sizes[i] == 32)        bp = (const float*)d_in[i];
    }
    if (!f || !Wp || !bp) {  // fallback positional
        f  = (const float*)d_in[0];
        Wp = (const float*)d_in[1];
        bp = (const float*)d_in[2];
    }
    float* out = (float*)d_out;

    att_kernel<<<HW_/TPB_A, TPB_A>>>(f, Wp, bp);
    dim3 gridB(NSPL, HW_/TPB_B);
    stream_kernel<<<gridB, TPB_B>>>(f, out);
}